// round 1
// baseline (speedup 1.0000x reference)
#include <cuda_runtime.h>

// 2D Haar DWT level kernel.
// For each output pixel (i,j) of one (batch, color) plane:
//   a = in[2i,2j], b = in[2i,2j+1], c = in[2i+1,2j], d = in[2i+1,2j+1]
//   L0=(a+c)/2, L1=(b+d)/2, H0=|a-c|, H1=|b-d|
//   LL=(L0+L1)/2, LH=|L0-L1|, HL=(H0+H1)/2, HH=|H0-H1|
// Outputs go to channels c*4 + {0,1,2,3} of a (B, 12, Ho, Wo) tensor.
// dup_g: when set and color==1 (green), also duplicate the 4 outputs into
// channels 8..11 (reference has b4 = g4 at level 4).
__global__ void dwt_level_kernel(const float* __restrict__ in,
                                 float* __restrict__ out,
                                 int Wo, int Ho,
                                 long in_b_stride, long in_c_stride, int nC,
                                 long out_b_stride, int dup_g)
{
    int j = blockIdx.x * blockDim.x + threadIdx.x;
    int i = blockIdx.y * blockDim.y + threadIdx.y;
    if (j >= Wo || i >= Ho) return;

    int bc = blockIdx.z;
    int b  = bc / nC;
    int c  = bc % nC;

    const float* ip = in + (long)b * in_b_stride + (long)c * in_c_stride;
    int Wi = Wo * 2;

    // Two adjacent input rows; float2 load gives (col 2j, col 2j+1), coalesced.
    const float2* r0 = reinterpret_cast<const float2*>(ip + (long)(2 * i) * Wi);
    const float2* r1 = reinterpret_cast<const float2*>(ip + (long)(2 * i + 1) * Wi);
    float2 t = __ldg(&r0[j]);
    float2 u = __ldg(&r1[j]);

    float a = t.x, bb = t.y, cc = u.x, dd = u.y;

    float L0 = (a + cc) * 0.5f;
    float L1 = (bb + dd) * 0.5f;
    float H0 = fabsf(a - cc);
    float H1 = fabsf(bb - dd);

    float LL = (L0 + L1) * 0.5f;
    float LH = fabsf(L0 - L1);
    float HL = (H0 + H1) * 0.5f;
    float HH = fabsf(H0 - H1);

    long plane = (long)Ho * Wo;
    float* op = out + (long)b * out_b_stride + (long)(c * 4) * plane
                    + (long)i * Wo + j;
    op[0]         = LL;
    op[plane]     = LH;
    op[2 * plane] = HL;
    op[3 * plane] = HH;

    if (dup_g && c == 1) {
        float* op2 = op + 4 * plane;   // channels 8..11
        op2[0]         = LL;
        op2[plane]     = LH;
        op2[2 * plane] = HL;
        op2[3 * plane] = HH;
    }
}

static inline void launch_level(const float* in, float* out,
                                int Wo, int Ho,
                                long in_b_stride, long in_c_stride, int nC,
                                long out_b_stride, int dup_g, int B)
{
    dim3 block(32, 8, 1);
    dim3 grid((Wo + 31) / 32, (Ho + 7) / 8, B * nC);
    dwt_level_kernel<<<grid, block>>>(in, out, Wo, Ho,
                                      in_b_stride, in_c_stride, nC,
                                      out_b_stride, dup_g);
}

extern "C" void kernel_launch(void* const* d_in, const int* in_sizes, int n_in,
                              void* d_out, int out_size)
{
    const float* x = (const float*)d_in[0];   // (32, 3, 512, 512) fp32
    float* out = (float*)d_out;

    const int B = 32;

    // Output segment offsets (tuple concat order: t1, t2, t3, t4)
    const long S1 = (long)B * 12 * 256 * 256;   // 25,165,824
    const long S2 = (long)B * 12 * 128 * 128;   //  6,291,456
    const long S3 = (long)B * 12 * 64 * 64;     //  1,572,864

    float* t1 = out;
    float* t2 = out + S1;
    float* t3 = out + S1 + S2;
    float* t4 = out + S1 + S2 + S3;

    // Level 1: x (B,3,512,512) -> t1 (B,12,256,256)
    launch_level(x, t1, 256, 256,
                 (long)3 * 512 * 512, (long)512 * 512, 3,
                 (long)12 * 256 * 256, 0, B);

    // Level 2: LL planes of t1 (channel c*4) -> t2 (B,12,128,128)
    launch_level(t1, t2, 128, 128,
                 (long)12 * 256 * 256, (long)4 * 256 * 256, 3,
                 (long)12 * 128 * 128, 0, B);

    // Level 3: LL planes of t2 -> t3 (B,12,64,64)
    launch_level(t2, t3, 64, 64,
                 (long)12 * 128 * 128, (long)4 * 128 * 128, 3,
                 (long)12 * 64 * 64, 0, B);

    // Level 4: LL planes of t3, r and g only (b4 = g4) -> t4 (B,12,32,32)
    launch_level(t3, t4, 32, 32,
                 (long)12 * 64 * 64, (long)4 * 64 * 64, 2,
                 (long)12 * 32 * 32, 1, B);
}

// round 2
// speedup vs baseline: 1.2479x; 1.2479x over previous
#include <cuda_runtime.h>

// Fully-fused 4-level 2D Haar DWT.
// Input x: (32, 3, 512, 512) fp32.
// Output: concat of t1 (32,12,256,256), t2 (32,12,128,128),
//         t3 (32,12,64,64), t4 (32,12,32,32).
// Each block processes one 128x128 input tile of one (batch, color) plane and
// cascades: L1 64x64 -> L2 32x32 -> L3 16x16 -> L4 8x8, LL bands in smem.
// Level 4: only r (c=0) and g (c=1) computed; blue slot duplicates g (b4=g4).

#define HAAR(a_, b_, c_, d_, LL, LH, HL, HH)      \
    do {                                          \
        float L0 = (a_ + c_) * 0.5f;              \
        float L1 = (b_ + d_) * 0.5f;              \
        float H0 = fabsf(a_ - c_);                \
        float H1 = fabsf(b_ - d_);                \
        LL = (L0 + L1) * 0.5f;                    \
        LH = fabsf(L0 - L1);                      \
        HL = (H0 + H1) * 0.5f;                    \
        HH = fabsf(H0 - H1);                      \
    } while (0)

__global__ __launch_bounds__(256) void dwt_fused_kernel(
    const float* __restrict__ x, float* __restrict__ out)
{
    __shared__ float s1[64 * 64];   // 16 KB, L1 LL
    __shared__ float s2[32 * 32];   //  4 KB, L2 LL
    __shared__ float s3[16 * 16];   //  1 KB, L3 LL

    const int tid = threadIdx.x;
    const int tj  = blockIdx.x;       // 0..3  (column tile)
    const int ti  = blockIdx.y;       // 0..3  (row tile)
    const int bc  = blockIdx.z;       // 0..95
    const int b   = bc / 3;
    const int c   = bc % 3;

    // Output segment bases (element offsets)
    const long S1 = 32L * 12 * 256 * 256;   // after t1
    const long S2 = 32L * 12 * 128 * 128;   // after t2
    const long S3 = 32L * 12 * 64 * 64;     // after t3

    // ---------------- Level 1: x -> t1 (64x64 outputs per block) -----------
    {
        const float* ip = x + (long)b * (3 * 512 * 512)
                            + (long)c * (512 * 512)
                            + (long)(ti * 128) * 512 + tj * 128;
        float* o1 = out + (long)b * (12 * 65536)
                        + (long)(c * 4) * 65536
                        + (long)(ti * 64) * 256 + tj * 64;

        const int tx = tid & 63;       // column 0..63
        const int ty = tid >> 6;       // 0..3

        #pragma unroll
        for (int r = ty; r < 64; r += 4) {
            const float2* r0 = reinterpret_cast<const float2*>(ip + (long)(2 * r) * 512);
            const float2* r1 = reinterpret_cast<const float2*>(ip + (long)(2 * r + 1) * 512);
            float2 t = __ldg(&r0[tx]);
            float2 u = __ldg(&r1[tx]);

            float LL, LH, HL, HH;
            HAAR(t.x, t.y, u.x, u.y, LL, LH, HL, HH);

            float* orow = o1 + (long)r * 256 + tx;
            orow[0]          = LL;
            orow[65536]      = LH;
            orow[2 * 65536]  = HL;
            orow[3 * 65536]  = HH;
            s1[r * 64 + tx]  = LL;
        }
    }
    __syncthreads();

    // ---------------- Level 2: s1 -> t2 (32x32 outputs) --------------------
    {
        float* o2 = out + S1 + (long)b * (12 * 16384)
                        + (long)(c * 4) * 16384
                        + (long)(ti * 32) * 128 + tj * 32;

        const int tx = tid & 31;       // column 0..31
        const int ty = tid >> 5;       // 0..7
        const float2* s1v = reinterpret_cast<const float2*>(s1);

        #pragma unroll
        for (int r = ty; r < 32; r += 8) {
            float2 t = s1v[(2 * r) * 32 + tx];
            float2 u = s1v[(2 * r + 1) * 32 + tx];

            float LL, LH, HL, HH;
            HAAR(t.x, t.y, u.x, u.y, LL, LH, HL, HH);

            float* orow = o2 + (long)r * 128 + tx;
            orow[0]          = LL;
            orow[16384]      = LH;
            orow[2 * 16384]  = HL;
            orow[3 * 16384]  = HH;
            s2[r * 32 + tx]  = LL;
        }
    }
    __syncthreads();

    // ---------------- Level 3: s2 -> t3 (16x16 outputs, 1/thread) ----------
    {
        float* o3 = out + S1 + S2 + (long)b * (12 * 4096)
                        + (long)(c * 4) * 4096
                        + (long)(ti * 16) * 64 + tj * 16;

        const int tx = tid & 15;       // 0..15
        const int ty = tid >> 4;       // 0..15
        const float2* s2v = reinterpret_cast<const float2*>(s2);

        float2 t = s2v[(2 * ty) * 16 + tx];
        float2 u = s2v[(2 * ty + 1) * 16 + tx];

        float LL, LH, HL, HH;
        HAAR(t.x, t.y, u.x, u.y, LL, LH, HL, HH);

        float* orow = o3 + (long)ty * 64 + tx;
        orow[0]         = LL;
        orow[4096]      = LH;
        orow[2 * 4096]  = HL;
        orow[3 * 4096]  = HH;
        s3[ty * 16 + tx] = LL;
    }
    __syncthreads();

    // ---------------- Level 4: s3 -> t4 (8x8 outputs, r & g only) ----------
    if (tid < 64 && c < 2) {
        float* o4 = out + S1 + S2 + S3 + (long)b * (12 * 1024)
                        + (long)(c * 4) * 1024
                        + (long)(ti * 8) * 32 + tj * 8;

        const int tx = tid & 7;        // 0..7
        const int ty = tid >> 3;       // 0..7
        const float2* s3v = reinterpret_cast<const float2*>(s3);

        float2 t = s3v[(2 * ty) * 8 + tx];
        float2 u = s3v[(2 * ty + 1) * 8 + tx];

        float LL, LH, HL, HH;
        HAAR(t.x, t.y, u.x, u.y, LL, LH, HL, HH);

        float* orow = o4 + (long)ty * 32 + tx;
        orow[0]         = LL;
        orow[1024]      = LH;
        orow[2 * 1024]  = HL;
        orow[3 * 1024]  = HH;

        if (c == 1) {                  // b4 = g4 -> channels 8..11
            float* orow2 = orow + 4 * 1024;
            orow2[0]         = LL;
            orow2[1024]      = LH;
            orow2[2 * 1024]  = HL;
            orow2[3 * 1024]  = HH;
        }
    }
}

extern "C" void kernel_launch(void* const* d_in, const int* in_sizes, int n_in,
                              void* d_out, int out_size)
{
    const float* x = (const float*)d_in[0];
    float* out = (float*)d_out;

    dim3 block(256, 1, 1);
    dim3 grid(4, 4, 96);   // (col tile, row tile, batch*color)
    dwt_fused_kernel<<<grid, block>>>(x, out);
}

// round 3
// speedup vs baseline: 1.2615x; 1.0109x over previous
#include <cuda_runtime.h>

// Fully-fused 4-level 2D Haar DWT, vectorized float4 version.
// Input x: (32, 3, 512, 512) fp32.
// Output: concat of t1 (32,12,256,256), t2 (32,12,128,128),
//         t3 (32,12,64,64), t4 (32,12,32,32).
// One block = one 128x128 input tile of one (batch,color) plane; LL bands
// cascade through shared memory. Level 4 computes r,g only (b4 = g4).

#define HAAR(a_, b_, c_, d_, LL, LH, HL, HH)      \
    do {                                          \
        float L0 = (a_ + c_) * 0.5f;              \
        float L1 = (b_ + d_) * 0.5f;              \
        float H0 = fabsf(a_ - c_);                \
        float H1 = fabsf(b_ - d_);                \
        LL = (L0 + L1) * 0.5f;                    \
        LH = fabsf(L0 - L1);                      \
        HL = (H0 + H1) * 0.5f;                    \
        HH = fabsf(H0 - H1);                      \
    } while (0)

// 4 horizontal Haar butterflies from two float4 row segments.
#define HAAR4(p0, p1, q0, q1, LL, LH, HL, HH)                     \
    do {                                                          \
        HAAR(p0.x, p0.y, q0.x, q0.y, LL.x, LH.x, HL.x, HH.x);     \
        HAAR(p0.z, p0.w, q0.z, q0.w, LL.y, LH.y, HL.y, HH.y);     \
        HAAR(p1.x, p1.y, q1.x, q1.y, LL.z, LH.z, HL.z, HH.z);     \
        HAAR(p1.z, p1.w, q1.z, q1.w, LL.w, LH.w, HL.w, HH.w);     \
    } while (0)

__global__ __launch_bounds__(256) void dwt_fused_kernel(
    const float* __restrict__ x, float* __restrict__ out)
{
    __shared__ float s1[64 * 64];   // 16 KB, L1 LL
    __shared__ float s2[32 * 32];   //  4 KB, L2 LL
    __shared__ float s3[16 * 16];   //  1 KB, L3 LL

    const int tid = threadIdx.x;
    const int tj  = blockIdx.x;       // 0..3
    const int ti  = blockIdx.y;       // 0..3
    const int bc  = blockIdx.z;       // 0..95
    const int b   = bc / 3;
    const int c   = bc % 3;

    const long S1 = 32L * 12 * 256 * 256;
    const long S2 = 32L * 12 * 128 * 128;
    const long S3 = 32L * 12 * 64 * 64;

    // ---- Level 1: x -> t1. 4 output px/thread/iter, LDG.128 / STG.128 ----
    {
        const float* ip = x + (long)b * (3 * 512 * 512)
                            + (long)c * (512 * 512)
                            + (long)(ti * 128) * 512 + tj * 128;
        float* o1 = out + (long)b * (12 * 65536)
                        + (long)(c * 4) * 65536
                        + (long)(ti * 64) * 256 + tj * 64;

        const int tx = tid & 15;      // 16 thread-cols * 4 out px = 64
        const int ty = tid >> 4;      // 0..15

        #pragma unroll
        for (int r = ty; r < 64; r += 16) {     // 4 iterations
            const float4* r0 = reinterpret_cast<const float4*>(ip + (long)(2 * r) * 512);
            const float4* r1 = reinterpret_cast<const float4*>(ip + (long)(2 * r + 1) * 512);
            float4 p0 = __ldcs(&r0[2 * tx]);
            float4 p1 = __ldcs(&r0[2 * tx + 1]);
            float4 q0 = __ldcs(&r1[2 * tx]);
            float4 q1 = __ldcs(&r1[2 * tx + 1]);

            float4 LL, LH, HL, HH;
            HAAR4(p0, p1, q0, q1, LL, LH, HL, HH);

            float* orow = o1 + (long)r * 256 + tx * 4;
            __stcs(reinterpret_cast<float4*>(orow),              LL);
            __stcs(reinterpret_cast<float4*>(orow + 65536),      LH);
            __stcs(reinterpret_cast<float4*>(orow + 2 * 65536),  HL);
            __stcs(reinterpret_cast<float4*>(orow + 3 * 65536),  HH);
            *reinterpret_cast<float4*>(&s1[r * 64 + tx * 4]) = LL;
        }
    }
    __syncthreads();

    // ---- Level 2: s1 (64x64) -> t2. 32x32 outputs, 4 px/thread, 1 iter ---
    {
        float* o2 = out + S1 + (long)b * (12 * 16384)
                        + (long)(c * 4) * 16384
                        + (long)(ti * 32) * 128 + tj * 32;

        const int tx = tid & 7;       // 8 thread-cols * 4 px = 32
        const int ty = tid >> 3;      // 0..31 (= output row)

        const float4* s1v = reinterpret_cast<const float4*>(s1);  // 16 f4/row
        float4 p0 = s1v[(2 * ty) * 16 + 2 * tx];
        float4 p1 = s1v[(2 * ty) * 16 + 2 * tx + 1];
        float4 q0 = s1v[(2 * ty + 1) * 16 + 2 * tx];
        float4 q1 = s1v[(2 * ty + 1) * 16 + 2 * tx + 1];

        float4 LL, LH, HL, HH;
        HAAR4(p0, p1, q0, q1, LL, LH, HL, HH);

        float* orow = o2 + (long)ty * 128 + tx * 4;
        *reinterpret_cast<float4*>(orow)              = LL;
        *reinterpret_cast<float4*>(orow + 16384)      = LH;
        *reinterpret_cast<float4*>(orow + 2 * 16384)  = HL;
        *reinterpret_cast<float4*>(orow + 3 * 16384)  = HH;
        *reinterpret_cast<float4*>(&s2[ty * 32 + tx * 4]) = LL;
    }
    __syncthreads();

    // ---- Level 3: s2 (32x32) -> t3. 16x16 outputs, 4 px/thread, tid<64 ---
    if (tid < 64) {
        float* o3 = out + S1 + S2 + (long)b * (12 * 4096)
                        + (long)(c * 4) * 4096
                        + (long)(ti * 16) * 64 + tj * 16;

        const int tx = tid & 3;       // 4 thread-cols * 4 px = 16
        const int ty = tid >> 2;      // 0..15

        const float4* s2v = reinterpret_cast<const float4*>(s2);  // 8 f4/row
        float4 p0 = s2v[(2 * ty) * 8 + 2 * tx];
        float4 p1 = s2v[(2 * ty) * 8 + 2 * tx + 1];
        float4 q0 = s2v[(2 * ty + 1) * 8 + 2 * tx];
        float4 q1 = s2v[(2 * ty + 1) * 8 + 2 * tx + 1];

        float4 LL, LH, HL, HH;
        HAAR4(p0, p1, q0, q1, LL, LH, HL, HH);

        float* orow = o3 + (long)ty * 64 + tx * 4;
        *reinterpret_cast<float4*>(orow)             = LL;
        *reinterpret_cast<float4*>(orow + 4096)      = LH;
        *reinterpret_cast<float4*>(orow + 2 * 4096)  = HL;
        *reinterpret_cast<float4*>(orow + 3 * 4096)  = HH;
        *reinterpret_cast<float4*>(&s3[ty * 16 + tx * 4]) = LL;
    }
    __syncthreads();

    // ---- Level 4: s3 (16x16) -> t4. 8x8 outputs, r/g only, tid<16 --------
    if (tid < 16 && c < 2) {
        float* o4 = out + S1 + S2 + S3 + (long)b * (12 * 1024)
                        + (long)(c * 4) * 1024
                        + (long)(ti * 8) * 32 + tj * 8;

        const int tx = tid & 1;       // 2 thread-cols * 4 px = 8
        const int ty = tid >> 1;      // 0..7

        const float4* s3v = reinterpret_cast<const float4*>(s3);  // 4 f4/row
        float4 p0 = s3v[(2 * ty) * 4 + 2 * tx];
        float4 p1 = s3v[(2 * ty) * 4 + 2 * tx + 1];
        float4 q0 = s3v[(2 * ty + 1) * 4 + 2 * tx];
        float4 q1 = s3v[(2 * ty + 1) * 4 + 2 * tx + 1];

        float4 LL, LH, HL, HH;
        HAAR4(p0, p1, q0, q1, LL, LH, HL, HH);

        float* orow = o4 + (long)ty * 32 + tx * 4;
        *reinterpret_cast<float4*>(orow)             = LL;
        *reinterpret_cast<float4*>(orow + 1024)      = LH;
        *reinterpret_cast<float4*>(orow + 2 * 1024)  = HL;
        *reinterpret_cast<float4*>(orow + 3 * 1024)  = HH;

        if (c == 1) {   // b4 = g4 -> channels 8..11
            float* orow2 = orow + 4 * 1024;
            *reinterpret_cast<float4*>(orow2)             = LL;
            *reinterpret_cast<float4*>(orow2 + 1024)      = LH;
            *reinterpret_cast<float4*>(orow2 + 2 * 1024)  = HL;
            *reinterpret_cast<float4*>(orow2 + 3 * 1024)  = HH;
        }
    }
}

extern "C" void kernel_launch(void* const* d_in, const int* in_sizes, int n_in,
                              void* d_out, int out_size)
{
    const float* x = (const float*)d_in[0];
    float* out = (float*)d_out;

    dim3 block(256, 1, 1);
    dim3 grid(4, 4, 96);
    dwt_fused_kernel<<<grid, block>>>(x, out);
}